// round 15
// baseline (speedup 1.0000x reference)
#include <cuda_runtime.h>
#include <cuda_fp16.h>
#include <cstdint>

#define B_  8
#define S_  4096
#define H_  768
#define D_  64
#define BQ  128
#define BK  64
#define HSTR 72   // half-element smem row stride; (72/2) % 32 == 4 -> conflict-free frag LDS

// scratch (q,k,v stored as fp16; weights transposed fp32)
__device__ __half g_q [B_ * S_ * D_];        // [b*S + s][d]
__device__ __half g_k [B_ * S_ * D_];        // [b*S + s][d]
__device__ __half g_vt[B_ * D_ * S_];        // transposed: [b][d][s]
__device__ float  g_wt[3][D_ * H_];          // W^T: [n][k]

// split-K partial buffers: index pi = (b*32+qt)*3 + chunk
__device__ float g_po[8 * 32 * 3 * 128 * 64];   // unnormalized O
__device__ float g_pm[8 * 32 * 3 * 128];        // row max
__device__ float g_pl[8 * 32 * 3 * 128];        // row sum

#define NCHUNK(qt) ((qt) < 12 ? 1 : ((qt) < 24 ? 2 : 3))

__device__ __forceinline__ void mma16(float* c, unsigned a0, unsigned a1, unsigned a2, unsigned a3,
                                      unsigned b0, unsigned b1) {
    asm("mma.sync.aligned.m16n8k16.row.col.f32.f16.f16.f32 "
        "{%0,%1,%2,%3}, {%4,%5,%6,%7}, {%8,%9}, {%0,%1,%2,%3};"
        : "+f"(c[0]), "+f"(c[1]), "+f"(c[2]), "+f"(c[3])
        : "r"(a0), "r"(a1), "r"(a2), "r"(a3), "r"(b0), "r"(b1));
}

__device__ __forceinline__ void ldm_x4(unsigned& r0, unsigned& r1, unsigned& r2, unsigned& r3,
                                       uint32_t addr) {
    asm volatile("ldmatrix.sync.aligned.m8n8.x4.shared.b16 {%0,%1,%2,%3}, [%4];"
                 : "=r"(r0), "=r"(r1), "=r"(r2), "=r"(r3) : "r"(addr));
}
__device__ __forceinline__ uint32_t s2u(const void* p) {
    return (uint32_t)__cvta_generic_to_shared(p);
}

// float4 -> 4 halfs packed in uint2
__device__ __forceinline__ uint2 f4h4(float4 v) {
    __half2 lo = __floats2half2_rn(v.x, v.y);
    __half2 hi = __floats2half2_rn(v.z, v.w);
    uint2 r;
    r.x = *(unsigned*)&lo;
    r.y = *(unsigned*)&hi;
    return r;
}
__device__ __forceinline__ unsigned pack2(float a, float b) {
    __half2 h = __floats2half2_rn(a, b);
    return *(unsigned*)&h;
}

// ---------------------------------------------------------------------------
// Kernel 0: transpose W into g_wt
// ---------------------------------------------------------------------------
__global__ void wt_kernel(const float* __restrict__ Wq,
                          const float* __restrict__ Wk,
                          const float* __restrict__ Wv) {
    int idx = blockIdx.x * blockDim.x + threadIdx.x;
    if (idx >= D_ * H_) return;
    int n = idx / H_, k = idx % H_;
    g_wt[0][idx] = Wq[k * D_ + n];
    g_wt[1][idx] = Wk[k * D_ + n];
    g_wt[2][idx] = Wv[k * D_ + n];
}

// ---------------------------------------------------------------------------
// Kernel 1: QKV projection, fp16 mma m16n8k16 (proven R11 version).
// ---------------------------------------------------------------------------
#define QKV_SMEM ((BQ + 64) * HSTR * (int)sizeof(__half))

__global__ void __launch_bounds__(256, 2) qkv_kernel(
    const float* __restrict__ x,
    const float* __restrict__ bq, const float* __restrict__ bk, const float* __restrict__ bv)
{
    extern __shared__ __half smh[];
    __half* xs = smh;                  // [128][HSTR]
    __half* ws = smh + BQ * HSTR;      // [64][HSTR]

    const int p = blockIdx.y;
    const float* wt   = g_wt[p];
    const float* bias = (p == 0) ? bq : ((p == 1) ? bk : bv);

    const int tid = threadIdx.x;
    const int w = tid >> 5, lane = tid & 31, g = lane >> 2, t = lane & 3;
    const int row0 = blockIdx.x * BQ;

    float acc[8][4] = {};

    for (int k0 = 0; k0 < H_; k0 += 64) {
        __syncthreads();
        #pragma unroll
        for (int i = 0; i < 8; i++) {              // x tile 128x64 -> half
            int e = tid + i * 256;
            int r = e >> 4, c4 = (e & 15) * 4;
            float4 v = *(const float4*)&x[(size_t)(row0 + r) * H_ + k0 + c4];
            *(uint2*)&xs[r * HSTR + c4] = f4h4(v);
        }
        #pragma unroll
        for (int i = 0; i < 4; i++) {              // W^T tile 64x64 -> half
            int e = tid + i * 256;
            int r = e >> 4, c4 = (e & 15) * 4;
            float4 v = *(const float4*)&wt[(size_t)r * H_ + k0 + c4];
            *(uint2*)&ws[r * HSTR + c4] = f4h4(v);
        }
        __syncthreads();

        #pragma unroll
        for (int s = 0; s < 4; s++) {              // k = 16s .. 16s+15
            const int kc = 16 * s + 2 * t;
            unsigned a0 = *(unsigned*)&xs[(16 * w + g) * HSTR + kc];
            unsigned a1 = *(unsigned*)&xs[(16 * w + g + 8) * HSTR + kc];
            unsigned a2 = *(unsigned*)&xs[(16 * w + g) * HSTR + kc + 8];
            unsigned a3 = *(unsigned*)&xs[(16 * w + g + 8) * HSTR + kc + 8];
            #pragma unroll
            for (int j = 0; j < 8; j++) {
                unsigned b0 = *(unsigned*)&ws[(8 * j + g) * HSTR + kc];
                unsigned b1 = *(unsigned*)&ws[(8 * j + g) * HSTR + kc + 8];
                mma16(acc[j], a0, a1, a2, a3, b0, b1);
            }
        }
    }

    const int r_g = row0 + 16 * w + g;
    if (p < 2) {
        __half* out = (p == 0) ? g_q : g_k;
        #pragma unroll
        for (int j = 0; j < 8; j++) {
            int c = 8 * j + 2 * t;
            float b0v = __ldg(&bias[c]), b1v = __ldg(&bias[c + 1]);
            *(__half2*)&out[(size_t)r_g * D_ + c]       = __floats2half2_rn(acc[j][0] + b0v, acc[j][1] + b1v);
            *(__half2*)&out[(size_t)(r_g + 8) * D_ + c] = __floats2half2_rn(acc[j][2] + b0v, acc[j][3] + b1v);
        }
    } else {
        int b = r_g >> 12, s0 = r_g & (S_ - 1);
        __half* out = g_vt + (size_t)b * D_ * S_;
        #pragma unroll
        for (int j = 0; j < 8; j++) {
            int c = 8 * j + 2 * t;
            float b0v = __ldg(&bias[c]), b1v = __ldg(&bias[c + 1]);
            out[(size_t)c * S_ + s0]           = __float2half_rn(acc[j][0] + b0v);
            out[(size_t)(c + 1) * S_ + s0]     = __float2half_rn(acc[j][1] + b1v);
            out[(size_t)c * S_ + s0 + 8]       = __float2half_rn(acc[j][2] + b0v);
            out[(size_t)(c + 1) * S_ + s0 + 8] = __float2half_rn(acc[j][3] + b1v);
        }
    }
}

// ---------------------------------------------------------------------------
// Kernel 2: split-K causal flash attention chunk, fp16 mma,
// register-resident P + ldmatrix fragment loads (4 frags / instruction).
// smem: Qs[128] + Ks[64] + Vts[64], each [.][HSTR] halfs.
// ---------------------------------------------------------------------------
#define ASMEM ((BQ + BK + BK) * HSTR * (int)sizeof(__half))

__global__ void __launch_bounds__(256, 2) attn_chunk_kernel(float* __restrict__ out)
{
    extern __shared__ __half smh[];
    __half* Qs  = smh;
    __half* Ks  = Qs  + BQ * HSTR;
    __half* Vts = Ks  + BK * HSTR;

    // decode work item
    const int b  = blockIdx.x & 7;
    const int w_ = blockIdx.x >> 3;        // 0..59
    int qt, chunk;
    if (w_ < 24)      { qt = 23 - (w_ >> 1);        chunk = w_ & 1; }
    else if (w_ < 48) { int u = w_ - 24; qt = 24 + u / 3; chunk = u % 3; }
    else              { qt = 59 - w_;               chunk = 0; }
    const int nkt = 2 * qt + 2;
    const int nc  = NCHUNK(qt);
    const int base = nkt / nc, rem = nkt % nc;
    const int k0  = chunk * base + (chunk < rem ? chunk : rem);
    const int k1  = k0 + base + (chunk < rem ? 1 : 0);

    const int tid = threadIdx.x;
    const int w = tid >> 5, lane = tid & 31, g = lane >> 2, t = lane & 3;

    const __half* q  = g_q  + (size_t)b * S_ * D_;
    const __half* kp = g_k  + (size_t)b * S_ * D_;
    const __half* vt = g_vt + (size_t)b * D_ * S_;

    #pragma unroll
    for (int i = 0; i < 8; i++) {                 // Q tile 128x64 halfs (pure copy)
        int e = tid + i * 256;
        int r = e >> 4, c4 = (e & 15) * 4;
        *(uint2*)&Qs[r * HSTR + c4] = *(const uint2*)&q[(size_t)(qt * BQ + r) * D_ + c4];
    }

    // ldmatrix per-lane base addresses (loop-invariant)
    const int mrow = lane & 7, mi = lane >> 3;    // matrix row, matrix index
    // A (Qs, warp rows 16w..): matrices = rows{0-7,8-15} x k{0-7,8-15}
    const uint32_t qaddr = s2u(&Qs[(16 * w + mrow + 8 * (mi & 1)) * HSTR + (mi >> 1) * 8]);
    // B (Ks/Vts, rows 8j..): matrices at k-offsets {0,8,16,24} (+32 for second half)
    const uint32_t kaddr = s2u(&Ks [mrow * HSTR + mi * 8]);
    const uint32_t vaddr = s2u(&Vts[mrow * HSTR + mi * 8]);
    const uint32_t jstep = 8 * HSTR * sizeof(__half);   // advance 8 n-rows

    float o[8][4] = {};
    float m0 = -1e30f, m1 = -1e30f, l0 = 0.f, l1 = 0.f;
    const float scale = 0.125f;                   // 1/sqrt(64)

    for (int kt = k0; kt < k1; kt++) {
        __syncthreads();
        #pragma unroll
        for (int i = 0; i < 4; i++) {             // K tile 64x64 halfs
            int e = tid + i * 256;
            int r = e >> 4, c4 = (e & 15) * 4;
            *(uint2*)&Ks[r * HSTR + c4] = *(const uint2*)&kp[(size_t)(kt * BK + r) * D_ + c4];
        }
        #pragma unroll
        for (int i = 0; i < 4; i++) {             // V^T tile [d][key] halfs
            int e = tid + i * 256;
            int r = e >> 4, c4 = (e & 15) * 4;
            *(uint2*)&Vts[r * HSTR + c4] = *(const uint2*)&vt[(size_t)r * S_ + kt * BK + c4];
        }
        __syncthreads();

        // A-fragments for all 4 k-steps (4 ldmatrix.x4)
        unsigned qa[4][4];
        #pragma unroll
        for (int s = 0; s < 4; s++)
            ldm_x4(qa[s][0], qa[s][1], qa[s][2], qa[s][3], qaddr + s * 32);

        // S = Q K^T  (fp16 operands, fp32 accum); K b-frags via ldmatrix
        float sc[8][4] = {};
        #pragma unroll
        for (int j = 0; j < 8; j++) {
            unsigned kb[8];                       // [s=0..3] x {b0,b1}
            ldm_x4(kb[0], kb[1], kb[2], kb[3], kaddr + j * jstep);        // k 0..31
            ldm_x4(kb[4], kb[5], kb[6], kb[7], kaddr + j * jstep + 64);   // k 32..63
            #pragma unroll
            for (int s = 0; s < 4; s++)
                mma16(sc[j], qa[s][0], qa[s][1], qa[s][2], qa[s][3], kb[2 * s], kb[2 * s + 1]);
        }

        #pragma unroll
        for (int j = 0; j < 8; j++) {
            sc[j][0] *= scale; sc[j][1] *= scale; sc[j][2] *= scale; sc[j][3] *= scale;
        }
        if (kt >= nkt - 2) {                      // diagonal masking (global kt)
            const int row_g = qt * BQ + 16 * w + g;
            #pragma unroll
            for (int j = 0; j < 8; j++) {
                int key = kt * BK + 8 * j + 2 * t;
                if (key     > row_g)     sc[j][0] = -1e30f;
                if (key + 1 > row_g)     sc[j][1] = -1e30f;
                if (key     > row_g + 8) sc[j][2] = -1e30f;
                if (key + 1 > row_g + 8) sc[j][3] = -1e30f;
            }
        }

        // online softmax; rows g (regs 0,1) and g+8 (regs 2,3) in-warp
        float mt0 = -1e30f, mt1 = -1e30f;
        #pragma unroll
        for (int j = 0; j < 8; j++) {
            mt0 = fmaxf(mt0, fmaxf(sc[j][0], sc[j][1]));
            mt1 = fmaxf(mt1, fmaxf(sc[j][2], sc[j][3]));
        }
        mt0 = fmaxf(mt0, __shfl_xor_sync(~0u, mt0, 1));
        mt0 = fmaxf(mt0, __shfl_xor_sync(~0u, mt0, 2));
        mt1 = fmaxf(mt1, __shfl_xor_sync(~0u, mt1, 1));
        mt1 = fmaxf(mt1, __shfl_xor_sync(~0u, mt1, 2));
        float mn0 = fmaxf(m0, mt0), mn1 = fmaxf(m1, mt1);
        float c0 = __expf(m0 - mn0), c1 = __expf(m1 - mn1);
        m0 = mn0; m1 = mn1;

        // exp + pack P directly into PV A-fragments (no smem)
        unsigned pr0[8], pr1[8];                  // pr0: row g; pr1: row g+8 (cols 8j+2t,+1)
        float rs0 = 0.f, rs1 = 0.f;
        #pragma unroll
        for (int j = 0; j < 8; j++) {
            float e0 = __expf(sc[j][0] - mn0), e1 = __expf(sc[j][1] - mn0);
            float e2 = __expf(sc[j][2] - mn1), e3 = __expf(sc[j][3] - mn1);
            rs0 += e0 + e1; rs1 += e2 + e3;
            pr0[j] = pack2(e0, e1);
            pr1[j] = pack2(e2, e3);
        }
        rs0 += __shfl_xor_sync(~0u, rs0, 1); rs0 += __shfl_xor_sync(~0u, rs0, 2);
        rs1 += __shfl_xor_sync(~0u, rs1, 1); rs1 += __shfl_xor_sync(~0u, rs1, 2);
        l0 = l0 * c0 + rs0; l1 = l1 * c1 + rs1;
        #pragma unroll
        for (int j = 0; j < 8; j++) {
            o[j][0] *= c0; o[j][1] *= c0; o[j][2] *= c1; o[j][3] *= c1;
        }

        // O += P V : A-frag from regs; V b-frags via ldmatrix
        #pragma unroll
        for (int j = 0; j < 8; j++) {
            unsigned vb[8];
            ldm_x4(vb[0], vb[1], vb[2], vb[3], vaddr + j * jstep);
            ldm_x4(vb[4], vb[5], vb[6], vb[7], vaddr + j * jstep + 64);
            #pragma unroll
            for (int s = 0; s < 4; s++)
                mma16(o[j], pr0[2 * s], pr1[2 * s], pr0[2 * s + 1], pr1[2 * s + 1],
                      vb[2 * s], vb[2 * s + 1]);
        }
    }

    const int rl0 = 16 * w + g;                   // local rows rl0, rl0+8
    if (nc == 1) {
        float i0 = 1.f / l0, i1 = 1.f / l1;
        float* op = out + ((size_t)b * S_ + qt * BQ + rl0) * D_;
        #pragma unroll
        for (int j = 0; j < 8; j++) {
            int c = 8 * j + 2 * t;
            *(float2*)&op[c]          = make_float2(o[j][0] * i0, o[j][1] * i0);
            *(float2*)&op[8 * D_ + c] = make_float2(o[j][2] * i1, o[j][3] * i1);
        }
    } else {
        const int pi = (b * 32 + qt) * 3 + chunk;
        float* po = g_po + (size_t)pi * 128 * 64;
        #pragma unroll
        for (int j = 0; j < 8; j++) {
            int c = 8 * j + 2 * t;
            *(float2*)&po[rl0 * 64 + c]       = make_float2(o[j][0], o[j][1]);
            *(float2*)&po[(rl0 + 8) * 64 + c] = make_float2(o[j][2], o[j][3]);
        }
        if (t == 0) {
            g_pm[pi * 128 + rl0]     = m0;
            g_pm[pi * 128 + rl0 + 8] = m1;
            g_pl[pi * 128 + rl0]     = l0;
            g_pl[pi * 128 + rl0 + 8] = l1;
        }
    }
}

// ---------------------------------------------------------------------------
// Kernel 3: merge split-K partials for qt >= 12.  grid=(80,8), block=256.
// (proven R10 version, 7.5us)
// ---------------------------------------------------------------------------
__global__ void __launch_bounds__(256) merge_kernel(float* __restrict__ out)
{
    const int qt  = 12 + (blockIdx.x >> 2);
    const int sub = blockIdx.x & 3;
    const int b   = blockIdx.y;
    const int nc  = NCHUNK(qt);
    const int pib = (b * 32 + qt) * 3;

    #pragma unroll
    for (int it = 0; it < 2; it++) {
        const int e4 = sub * 512 + it * 256 + threadIdx.x;   // float4 index in [0,2048)
        const int e  = e4 * 4;
        const int r  = e >> 6, col = e & 63;

        float M = -1e30f;
        #pragma unroll
        for (int c = 0; c < 3; c++)
            if (c < nc) M = fmaxf(M, g_pm[(pib + c) * 128 + r]);
        float L = 0.f;
        float4 O = make_float4(0.f, 0.f, 0.f, 0.f);
        #pragma unroll
        for (int c = 0; c < 3; c++)
            if (c < nc) {
                float wgt = __expf(g_pm[(pib + c) * 128 + r] - M);
                L += g_pl[(pib + c) * 128 + r] * wgt;
                float4 v = *(const float4*)&g_po[(size_t)(pib + c) * 8192 + e];
                O.x += v.x * wgt; O.y += v.y * wgt; O.z += v.z * wgt; O.w += v.w * wgt;
            }
        float inv = 1.f / L;
        O.x *= inv; O.y *= inv; O.z *= inv; O.w *= inv;
        *(float4*)&out[((size_t)b * S_ + qt * BQ + r) * D_ + col] = O;
    }
}

// ---------------------------------------------------------------------------
extern "C" void kernel_launch(void* const* d_in, const int* in_sizes, int n_in,
                              void* d_out, int out_size)
{
    const float* x  = (const float*)d_in[0];
    const float* Wq = (const float*)d_in[1];
    const float* bq = (const float*)d_in[2];
    const float* Wk = (const float*)d_in[3];
    const float* bk = (const float*)d_in[4];
    const float* Wv = (const float*)d_in[5];
    const float* bv = (const float*)d_in[6];
    float* out = (float*)d_out;

    cudaFuncSetAttribute(qkv_kernel,        cudaFuncAttributeMaxDynamicSharedMemorySize, QKV_SMEM);
    cudaFuncSetAttribute(attn_chunk_kernel, cudaFuncAttributeMaxDynamicSharedMemorySize, ASMEM);

    wt_kernel<<<(D_ * H_ + 255) / 256, 256>>>(Wq, Wk, Wv);

    dim3 g1((B_ * S_) / BQ, 3);
    qkv_kernel<<<g1, 256, QKV_SMEM>>>(x, bq, bk, bv);

    attn_chunk_kernel<<<480, 256, ASMEM>>>(out);

    dim3 g3(80, 8);
    merge_kernel<<<g3, 256>>>(out);
}